// round 1
// baseline (speedup 1.0000x reference)
#include <cuda_runtime.h>
#include <math.h>

// Problem constants
static constexpr int Bc  = 2;
static constexpr int Sc  = 2048;
static constexpr int Dc  = 1024;
static constexpr int Hc  = 16;
static constexpr int HDc = 64;

static constexpr int Mtot = Bc * Sc;   // 4096
static constexpr int Ntot = Dc;        // 1024
static constexpr int Ktot = Dc;        // 1024

// Scratch (device globals: allocation-free rule)
__device__ float g_q[Bc * Hc * Sc * HDc];   // [B,H,S,HD]
__device__ float g_k[Bc * Hc * Sc * HDc];
__device__ float g_v[Bc * Hc * Sc * HDc];
__device__ float g_ctx[Bc * Sc * Dc];       // [B,S,D]

// ---------------------------------------------------------------------------
// SGEMM: C[M,N] = A[M,K] @ W[K,N] (+bias)*scale
// MODE 0: plain row-major output [M,N]
// MODE 1: permuted output [B,H,S,HD]  (m = b*S+s, n = h*HD+hd)
// 128x128 block tile, BK=8, 256 threads, 8x8 per-thread tile.
// ---------------------------------------------------------------------------
template <int MODE>
__global__ __launch_bounds__(256)
void sgemm128(const float* __restrict__ A, const float* __restrict__ W,
              const float* __restrict__ bias, float* __restrict__ C,
              float scale)
{
    __shared__ float As[8][128];   // As[k][m]  (A tile transposed)
    __shared__ float Bs[8][128];   // Bs[k][n]

    const int tid = threadIdx.x;
    const int bx  = blockIdx.x;    // N tile (0..7)
    const int by  = blockIdx.y;    // M tile (0..31)

    const int aRow = tid >> 1;          // 0..127
    const int aCol = (tid & 1) * 4;     // 0 or 4
    const int bRow = tid >> 5;          // 0..7
    const int bCol = (tid & 31) * 4;    // 0..124

    const int ty = tid >> 4;   // 0..15 -> rows ty*8..+7
    const int tx = tid & 15;   // 0..15 -> cols tx*8..+7

    const float* Aptr = A + (size_t)(by * 128 + aRow) * Ktot + aCol;
    const float* Wptr = W + (size_t)bRow * Ntot + bx * 128 + bCol;

    float acc[8][8];
#pragma unroll
    for (int i = 0; i < 8; i++)
#pragma unroll
        for (int j = 0; j < 8; j++) acc[i][j] = 0.f;

    for (int k0 = 0; k0 < Ktot; k0 += 8) {
        float4 av = *(const float4*)(Aptr + k0);
        float4 bv = *(const float4*)(Wptr + (size_t)k0 * Ntot);
        As[aCol + 0][aRow] = av.x;
        As[aCol + 1][aRow] = av.y;
        As[aCol + 2][aRow] = av.z;
        As[aCol + 3][aRow] = av.w;
        *(float4*)&Bs[bRow][bCol] = bv;
        __syncthreads();

#pragma unroll
        for (int kk = 0; kk < 8; kk++) {
            float a[8], b[8];
            *(float4*)&a[0] = *(const float4*)&As[kk][ty * 8];
            *(float4*)&a[4] = *(const float4*)&As[kk][ty * 8 + 4];
            *(float4*)&b[0] = *(const float4*)&Bs[kk][tx * 8];
            *(float4*)&b[4] = *(const float4*)&Bs[kk][tx * 8 + 4];
#pragma unroll
            for (int i = 0; i < 8; i++)
#pragma unroll
                for (int j = 0; j < 8; j++)
                    acc[i][j] += a[i] * b[j];
        }
        __syncthreads();
    }

    // Epilogue
#pragma unroll
    for (int i = 0; i < 8; i++) {
        const int m = by * 128 + ty * 8 + i;
#pragma unroll
        for (int j4 = 0; j4 < 8; j4 += 4) {
            const int n = bx * 128 + tx * 8 + j4;
            float4 r;
            r.x = (acc[i][j4 + 0] + bias[n + 0]) * scale;
            r.y = (acc[i][j4 + 1] + bias[n + 1]) * scale;
            r.z = (acc[i][j4 + 2] + bias[n + 2]) * scale;
            r.w = (acc[i][j4 + 3] + bias[n + 3]) * scale;
            if (MODE == 0) {
                *(float4*)&C[(size_t)m * Ntot + n] = r;
            } else {
                const int b  = m >> 11;        // m / 2048
                const int s  = m & 2047;
                const int h  = n >> 6;         // n / 64
                const int hd = n & 63;
                *(float4*)&C[(((size_t)(b * Hc + h) * Sc) + s) * HDc + hd] = r;
            }
        }
    }
}

// ---------------------------------------------------------------------------
// Flash attention (fp32): per block = one (b,h), 128-query tile.
// One query per thread; q-row and o accumulator in registers.
// KV tiles of 32 keys staged in smem (broadcast reads).
// Online softmax; ctx written directly in [B,S,D] layout.
// ---------------------------------------------------------------------------
__global__ __launch_bounds__(128)
void attn_kernel(const float* __restrict__ Q, const float* __restrict__ K,
                 const float* __restrict__ V, const float* __restrict__ mask,
                 float* __restrict__ Octx)
{
    __shared__ float Ks[32][64];
    __shared__ float Vs[32][64];
    __shared__ float Ss[128][33];   // padded: bank = (tid + j) % 32, conflict-free
    __shared__ float Ms[32];

    const int tid = threadIdx.x;
    const int bh  = blockIdx.y;       // 0..B*H-1
    const int b   = bh >> 4;
    const int h   = bh & 15;
    const int q   = blockIdx.x * 128 + tid;

    // Load this thread's query row into registers
    const float* qp = Q + ((size_t)bh * Sc + q) * HDc;
    float qr[64];
#pragma unroll
    for (int d4 = 0; d4 < 16; d4++)
        *(float4*)&qr[d4 * 4] = *(const float4*)(qp + d4 * 4);

    float o[64];
#pragma unroll
    for (int d = 0; d < 64; d++) o[d] = 0.f;
    float mmax = -1e30f, l = 0.f;

    const float* kbase = K + (size_t)bh * Sc * HDc;
    const float* vbase = V + (size_t)bh * Sc * HDc;
    const float* mbase = mask + (size_t)b * Sc;

    for (int kt = 0; kt < Sc; kt += 32) {
        // Stage K/V tile: 32 rows x 64 floats = 512 float4 each; 4 per thread
#pragma unroll
        for (int it = 0; it < 4; it++) {
            const int idx = tid + it * 128;     // 0..511
            const int r = idx >> 4;
            const int c = (idx & 15) * 4;
            *(float4*)&Ks[r][c] = *(const float4*)(kbase + (size_t)(kt + r) * HDc + c);
            *(float4*)&Vs[r][c] = *(const float4*)(vbase + (size_t)(kt + r) * HDc + c);
        }
        if (tid < 32) Ms[tid] = mbase[kt + tid];
        __syncthreads();

        // Scores for this tile (Q already scaled by 1/sqrt(HD))
        float mt = -1e30f;
        for (int j = 0; j < 32; j++) {
            float s = 0.f;
#pragma unroll
            for (int d4 = 0; d4 < 16; d4++) {
                float4 kv = *(const float4*)&Ks[j][d4 * 4];
                s += qr[d4 * 4 + 0] * kv.x;
                s += qr[d4 * 4 + 1] * kv.y;
                s += qr[d4 * 4 + 2] * kv.z;
                s += qr[d4 * 4 + 3] * kv.w;
            }
            s += Ms[j];
            Ss[tid][j] = s;
            mt = fmaxf(mt, s);
        }

        const float mnew  = fmaxf(mmax, mt);
        const float alpha = __expf(mmax - mnew);
        l *= alpha;
#pragma unroll
        for (int d = 0; d < 64; d++) o[d] *= alpha;

        for (int j = 0; j < 32; j++) {
            const float p = __expf(Ss[tid][j] - mnew);
            l += p;
#pragma unroll
            for (int d4 = 0; d4 < 16; d4++) {
                float4 vv = *(const float4*)&Vs[j][d4 * 4];
                o[d4 * 4 + 0] += p * vv.x;
                o[d4 * 4 + 1] += p * vv.y;
                o[d4 * 4 + 2] += p * vv.z;
                o[d4 * 4 + 3] += p * vv.w;
            }
        }
        mmax = mnew;
        __syncthreads();
    }

    const float inv = 1.f / l;
    float* op = Octx + ((size_t)b * Sc + q) * Dc + h * HDc;
#pragma unroll
    for (int d4 = 0; d4 < 16; d4++) {
        float4 r;
        r.x = o[d4 * 4 + 0] * inv;
        r.y = o[d4 * 4 + 1] * inv;
        r.z = o[d4 * 4 + 2] * inv;
        r.w = o[d4 * 4 + 3] * inv;
        *(float4*)(op + d4 * 4) = r;
    }
}

// ---------------------------------------------------------------------------
extern "C" void kernel_launch(void* const* d_in, const int* in_sizes, int n_in,
                              void* d_out, int out_size)
{
    const float* x    = (const float*)d_in[0];
    const float* mask = (const float*)d_in[1];
    const float* Wq   = (const float*)d_in[2];
    const float* bq   = (const float*)d_in[3];
    const float* Wk   = (const float*)d_in[4];
    const float* bk   = (const float*)d_in[5];
    const float* Wv   = (const float*)d_in[6];
    const float* bv   = (const float*)d_in[7];
    const float* Wo   = (const float*)d_in[8];
    const float* bo   = (const float*)d_in[9];
    float* out = (float*)d_out;

    void *qv, *kv, *vv, *cv;
    cudaGetSymbolAddress(&qv, g_q);
    cudaGetSymbolAddress(&kv, g_k);
    cudaGetSymbolAddress(&vv, g_v);
    cudaGetSymbolAddress(&cv, g_ctx);
    float* q   = (float*)qv;
    float* k   = (float*)kv;
    float* v   = (float*)vv;
    float* ctx = (float*)cv;

    const float qscale = 0.125f;   // 1/sqrt(64)

    dim3 ggrid(Ntot / 128, Mtot / 128);   // (8, 32)
    dim3 gblk(256);

    sgemm128<1><<<ggrid, gblk>>>(x, Wq, bq, q, qscale);
    sgemm128<1><<<ggrid, gblk>>>(x, Wk, bk, k, 1.0f);
    sgemm128<1><<<ggrid, gblk>>>(x, Wv, bv, v, 1.0f);

    dim3 agrid(Sc / 128, Bc * Hc);        // (16, 32)
    attn_kernel<<<agrid, 128>>>(q, k, v, mask, ctx);

    sgemm128<0><<<ggrid, gblk>>>(ctx, Wo, bo, out, 1.0f);
}

// round 4
// speedup vs baseline: 3.7778x; 3.7778x over previous
#include <cuda_runtime.h>
#include <math.h>

static constexpr int Bc  = 2;
static constexpr int Sc  = 2048;
static constexpr int Dc  = 1024;
static constexpr int Hc  = 16;
static constexpr int HDc = 64;
static constexpr int Mtot = Bc * Sc;   // 4096

// Scratch (device globals: allocation-free rule). ~67MB total.
__device__ float g_q[(size_t)Bc * Hc * Sc * HDc];      // [B,H,S,HD]
__device__ float g_k[(size_t)Bc * Hc * Sc * HDc];
__device__ float g_v[(size_t)Bc * Hc * Sc * HDc];
__device__ float g_ctx[(size_t)Bc * Sc * Dc];          // [B,S,D]

// ---------------------------------------------------------------------------
// tf32 helpers
// ---------------------------------------------------------------------------
__device__ __forceinline__ unsigned f2tf(float x) {
    unsigned r;
    asm("cvt.rna.tf32.f32 %0, %1;" : "=r"(r) : "f"(x));
    return r;
}

__device__ __forceinline__ void mma8(float c[4], const unsigned a[4], const unsigned b[2]) {
    asm volatile(
        "mma.sync.aligned.m16n8k8.row.col.f32.tf32.tf32.f32 "
        "{%0,%1,%2,%3}, {%4,%5,%6,%7}, {%8,%9}, {%0,%1,%2,%3};"
        : "+f"(c[0]), "+f"(c[1]), "+f"(c[2]), "+f"(c[3])
        : "r"(a[0]), "r"(a[1]), "r"(a[2]), "r"(a[3]), "r"(b[0]), "r"(b[1]));
}

// ---------------------------------------------------------------------------
// tf32 MMA GEMM: C = A[M,K] @ B[K,N] + bias  (projections)
// EPI 0: row-major C[m*ldc+n] = acc + bias[n]
// EPI 1: permuted [B,H,S,HD] <- (acc + bias[n]) * scale
// 128x128x32 block tile, warps 2x4 (64x32), 256 threads.
// ---------------------------------------------------------------------------
template <int EPI>
__global__ __launch_bounds__(256)
void mma_gemm(const float* __restrict__ A, const float* __restrict__ B,
              const float* __restrict__ bias, float* __restrict__ C,
              float scale)
{
    constexpr int BM = 128, BN = 128, BK = 32;
    constexpr int MI = 4, NI = 4;   // WM=64, WN=32
    constexpr int Kd = 1024;

    __shared__ unsigned As[BK][BM + 8];
    __shared__ unsigned Bs[BK][BN + 8];

    const int tid = threadIdx.x;
    const int m0 = blockIdx.y * BM;
    const int n0 = blockIdx.x * BN;

    const int w    = tid >> 5;
    const int lane = tid & 31;
    const int wr   = w & 1;         // BM/WM = 2
    const int wc   = w >> 1;        // 0..3
    const int lg   = lane >> 2;
    const int lt   = lane & 3;

    float acc[MI][NI][4];
#pragma unroll
    for (int mi = 0; mi < MI; mi++)
#pragma unroll
        for (int ni = 0; ni < NI; ni++)
#pragma unroll
            for (int r = 0; r < 4; r++) acc[mi][ni][r] = 0.f;

    for (int k0 = 0; k0 < Kd; k0 += BK) {
#pragma unroll
        for (int i = 0; i < 4; i++) {
            const int id = tid + i * 256;
            const int r  = id >> 3;         // /(BK/4)
            const int c4 = id & 7;
            float4 v = *(const float4*)(A + (size_t)(m0 + r) * Kd + k0 + c4 * 4);
            As[c4 * 4 + 0][r] = f2tf(v.x);
            As[c4 * 4 + 1][r] = f2tf(v.y);
            As[c4 * 4 + 2][r] = f2tf(v.z);
            As[c4 * 4 + 3][r] = f2tf(v.w);
        }
#pragma unroll
        for (int i = 0; i < 4; i++) {
            const int id = tid + i * 256;
            const int r  = id >> 5;         // /(BN/4)
            const int c4 = id & 31;
            float4 v = *(const float4*)(B + (size_t)(k0 + r) * Dc + n0 + c4 * 4);
            Bs[r][c4 * 4 + 0] = f2tf(v.x);
            Bs[r][c4 * 4 + 1] = f2tf(v.y);
            Bs[r][c4 * 4 + 2] = f2tf(v.z);
            Bs[r][c4 * 4 + 3] = f2tf(v.w);
        }
        __syncthreads();

#pragma unroll
        for (int kk = 0; kk < BK; kk += 8) {
            unsigned af[MI][4], bf[NI][2];
#pragma unroll
            for (int mi = 0; mi < MI; mi++) {
                const int rb = wr * 64 + mi * 16;
                af[mi][0] = As[kk + lt    ][rb + lg    ];
                af[mi][1] = As[kk + lt    ][rb + lg + 8];
                af[mi][2] = As[kk + lt + 4][rb + lg    ];
                af[mi][3] = As[kk + lt + 4][rb + lg + 8];
            }
#pragma unroll
            for (int ni = 0; ni < NI; ni++) {
                const int nb = wc * 32 + ni * 8;
                bf[ni][0] = Bs[kk + lt    ][nb + lg];
                bf[ni][1] = Bs[kk + lt + 4][nb + lg];
            }
#pragma unroll
            for (int mi = 0; mi < MI; mi++)
#pragma unroll
                for (int ni = 0; ni < NI; ni++)
                    mma8(acc[mi][ni], af[mi], bf[ni]);
        }
        __syncthreads();
    }

#pragma unroll
    for (int mi = 0; mi < MI; mi++) {
#pragma unroll
        for (int ni = 0; ni < NI; ni++) {
            const int gmb = m0 + wr * 64 + mi * 16 + lg;
            const int gn  = n0 + wc * 32 + ni * 8 + lt * 2;
#pragma unroll
            for (int hh = 0; hh < 2; hh++) {
                const int gm = gmb + hh * 8;
                const float v0 = acc[mi][ni][hh * 2 + 0];
                const float v1 = acc[mi][ni][hh * 2 + 1];
                if (EPI == 0) {
                    *(float2*)&C[(size_t)gm * Dc + gn] =
                        make_float2(v0 + bias[gn], v1 + bias[gn + 1]);
                } else {
                    float2 r = make_float2((v0 + bias[gn]) * scale,
                                           (v1 + bias[gn + 1]) * scale);
                    const int b = gm >> 11, s = gm & 2047;
                    const int hd = gn & 63, hq = gn >> 6;
                    *(float2*)&C[(((size_t)(b * Hc + hq) * Sc) + s) * HDc + hd] = r;
                }
            }
        }
    }
}

// ---------------------------------------------------------------------------
// Fused tensor-core flash attention (tf32 MMA, fp32 accum).
// Block: one (b,h), 128 queries; 8 warps x 16 rows. Key tiles of 64.
// Q pre-scaled by 1/sqrt(HD). Softmax fully warp-local (quad shuffles).
// P C-frag -> A-frag conversion via register shuffles (no smem roundtrip).
// ---------------------------------------------------------------------------
__global__ __launch_bounds__(256)
void fattn(const float* __restrict__ Q, const float* __restrict__ K,
           const float* __restrict__ V, const float* __restrict__ mask,
           float* __restrict__ Octx)
{
    __shared__ unsigned Ks[64][72];   // [hd][key] tf32
    __shared__ unsigned Vs[64][72];   // [key][hd] tf32
    __shared__ float    Msk[64];

    const int tid  = threadIdx.x;
    const int w    = tid >> 5;
    const int lane = tid & 31;
    const int lg   = lane >> 2;
    const int lt   = lane & 3;

    const int bh = blockIdx.y;
    const int b  = bh >> 4;
    const int h  = bh & 15;
    const int q0 = blockIdx.x * 128 + w * 16;

    // Q fragments (one-time gmem gather, rows q0+lg / q0+lg+8)
    const float* Qb = Q + ((size_t)bh * Sc + q0) * HDc;
    unsigned qf[8][4];
#pragma unroll
    for (int kf = 0; kf < 8; kf++) {
        qf[kf][0] = f2tf(__ldg(Qb + (size_t)(lg    ) * HDc + kf * 8 + lt    ));
        qf[kf][1] = f2tf(__ldg(Qb + (size_t)(lg + 8) * HDc + kf * 8 + lt    ));
        qf[kf][2] = f2tf(__ldg(Qb + (size_t)(lg    ) * HDc + kf * 8 + lt + 4));
        qf[kf][3] = f2tf(__ldg(Qb + (size_t)(lg + 8) * HDc + kf * 8 + lt + 4));
    }

    float acc_o[8][4];
#pragma unroll
    for (int no = 0; no < 8; no++)
#pragma unroll
        for (int r = 0; r < 4; r++) acc_o[no][r] = 0.f;
    float m_lo = -1e30f, m_hi = -1e30f, l_lo = 0.f, l_hi = 0.f;

    const float* Kb = K + (size_t)bh * Sc * HDc;
    const float* Vb = V + (size_t)bh * Sc * HDc;
    const float* Mb = mask + (size_t)b * Sc;

    for (int kt = 0; kt < Sc; kt += 64) {
        // ---- stage mask + K (transposed) + V (natural) tiles ----
        if (tid < 64) Msk[tid] = Mb[kt + tid];
#pragma unroll
        for (int i = 0; i < 4; i++) {
            const int idx = tid + i * 256;          // 0..1023
            {
                const int key = idx & 63;
                const int h4  = idx >> 6;           // 0..15
                float4 kv = *(const float4*)(Kb + (size_t)(kt + key) * HDc + h4 * 4);
                Ks[h4 * 4 + 0][key] = f2tf(kv.x);
                Ks[h4 * 4 + 1][key] = f2tf(kv.y);
                Ks[h4 * 4 + 2][key] = f2tf(kv.z);
                Ks[h4 * 4 + 3][key] = f2tf(kv.w);
            }
            {
                const int key = idx >> 4;           // 0..63
                const int h4  = idx & 15;
                float4 vv = *(const float4*)(Vb + (size_t)(kt + key) * HDc + h4 * 4);
                *(uint4*)&Vs[key][h4 * 4] =
                    make_uint4(f2tf(vv.x), f2tf(vv.y), f2tf(vv.z), f2tf(vv.w));
            }
        }
        __syncthreads();

        // ---- S = Q K^T (16 rows x 64 keys per warp) ----
        float sc[8][4];
#pragma unroll
        for (int ni = 0; ni < 8; ni++)
#pragma unroll
            for (int r = 0; r < 4; r++) sc[ni][r] = 0.f;
#pragma unroll
        for (int kf = 0; kf < 8; kf++) {
#pragma unroll
            for (int ni = 0; ni < 8; ni++) {
                unsigned bf[2];
                bf[0] = Ks[kf * 8 + lt    ][ni * 8 + lg];
                bf[1] = Ks[kf * 8 + lt + 4][ni * 8 + lg];
                mma8(sc[ni], qf[kf], bf);
            }
        }

        // ---- mask + online softmax (quad-local) ----
        float rmax_lo = -1e30f, rmax_hi = -1e30f;
#pragma unroll
        for (int ni = 0; ni < 8; ni++) {
            const float mk0 = Msk[ni * 8 + 2 * lt];
            const float mk1 = Msk[ni * 8 + 2 * lt + 1];
            sc[ni][0] += mk0; sc[ni][1] += mk1;
            sc[ni][2] += mk0; sc[ni][3] += mk1;
            rmax_lo = fmaxf(rmax_lo, fmaxf(sc[ni][0], sc[ni][1]));
            rmax_hi = fmaxf(rmax_hi, fmaxf(sc[ni][2], sc[ni][3]));
        }
        rmax_lo = fmaxf(rmax_lo, __shfl_xor_sync(0xffffffffu, rmax_lo, 1));
        rmax_lo = fmaxf(rmax_lo, __shfl_xor_sync(0xffffffffu, rmax_lo, 2));
        rmax_hi = fmaxf(rmax_hi, __shfl_xor_sync(0xffffffffu, rmax_hi, 1));
        rmax_hi = fmaxf(rmax_hi, __shfl_xor_sync(0xffffffffu, rmax_hi, 2));

        const float mn_lo = fmaxf(m_lo, rmax_lo);
        const float mn_hi = fmaxf(m_hi, rmax_hi);
        const float al_lo = __expf(m_lo - mn_lo);
        const float al_hi = __expf(m_hi - mn_hi);
        m_lo = mn_lo; m_hi = mn_hi;

        float ps_lo = 0.f, ps_hi = 0.f;
#pragma unroll
        for (int ni = 0; ni < 8; ni++) {
            sc[ni][0] = __expf(sc[ni][0] - m_lo);
            sc[ni][1] = __expf(sc[ni][1] - m_lo);
            sc[ni][2] = __expf(sc[ni][2] - m_hi);
            sc[ni][3] = __expf(sc[ni][3] - m_hi);
            ps_lo += sc[ni][0] + sc[ni][1];
            ps_hi += sc[ni][2] + sc[ni][3];
        }
        l_lo = l_lo * al_lo + ps_lo;
        l_hi = l_hi * al_hi + ps_hi;
#pragma unroll
        for (int no = 0; no < 8; no++) {
            acc_o[no][0] *= al_lo; acc_o[no][1] *= al_lo;
            acc_o[no][2] *= al_hi; acc_o[no][3] *= al_hi;
        }

        // ---- PV: convert P C-frag -> A-frag via shuffles, then MMA ----
        const int src_lo = (lane & 28) | (lt >> 1);
        const int src_hi = src_lo + 2;
#pragma unroll
        for (int kf = 0; kf < 8; kf++) {
            unsigned a[4];
            {
                float v0 = __shfl_sync(0xffffffffu, sc[kf][0], src_lo);
                float v1 = __shfl_sync(0xffffffffu, sc[kf][1], src_lo);
                a[0] = f2tf((lt & 1) ? v1 : v0);
                float v2 = __shfl_sync(0xffffffffu, sc[kf][2], src_lo);
                float v3 = __shfl_sync(0xffffffffu, sc[kf][3], src_lo);
                a[1] = f2tf((lt & 1) ? v3 : v2);
                float u0 = __shfl_sync(0xffffffffu, sc[kf][0], src_hi);
                float u1 = __shfl_sync(0xffffffffu, sc[kf][1], src_hi);
                a[2] = f2tf((lt & 1) ? u1 : u0);
                float u2 = __shfl_sync(0xffffffffu, sc[kf][2], src_hi);
                float u3 = __shfl_sync(0xffffffffu, sc[kf][3], src_hi);
                a[3] = f2tf((lt & 1) ? u3 : u2);
            }
#pragma unroll
            for (int no = 0; no < 8; no++) {
                unsigned bf[2];
                bf[0] = Vs[kf * 8 + lt    ][no * 8 + lg];
                bf[1] = Vs[kf * 8 + lt + 4][no * 8 + lg];
                mma8(acc_o[no], a, bf);
            }
        }
        __syncthreads();
    }

    // ---- finalize: normalize and write ctx [B,S,D] ----
    l_lo += __shfl_xor_sync(0xffffffffu, l_lo, 1);
    l_lo += __shfl_xor_sync(0xffffffffu, l_lo, 2);
    l_hi += __shfl_xor_sync(0xffffffffu, l_hi, 1);
    l_hi += __shfl_xor_sync(0xffffffffu, l_hi, 2);
    const float inv_lo = 1.f / l_lo;
    const float inv_hi = 1.f / l_hi;

    float* Ob = Octx + ((size_t)b * Sc + q0) * Dc + h * HDc;
#pragma unroll
    for (int no = 0; no < 8; no++) {
        const int col = no * 8 + 2 * lt;
        *(float2*)(Ob + (size_t)(lg    ) * Dc + col) =
            make_float2(acc_o[no][0] * inv_lo, acc_o[no][1] * inv_lo);
        *(float2*)(Ob + (size_t)(lg + 8) * Dc + col) =
            make_float2(acc_o[no][2] * inv_hi, acc_o[no][3] * inv_hi);
    }
}

// ---------------------------------------------------------------------------
extern "C" void kernel_launch(void* const* d_in, const int* in_sizes, int n_in,
                              void* d_out, int out_size)
{
    const float* x    = (const float*)d_in[0];
    const float* mask = (const float*)d_in[1];
    const float* Wq   = (const float*)d_in[2];
    const float* bq   = (const float*)d_in[3];
    const float* Wk   = (const float*)d_in[4];
    const float* bk   = (const float*)d_in[5];
    const float* Wv   = (const float*)d_in[6];
    const float* bv   = (const float*)d_in[7];
    const float* Wo   = (const float*)d_in[8];
    const float* bo   = (const float*)d_in[9];
    float* out = (float*)d_out;

    void *qv, *kv, *vv, *cv;
    cudaGetSymbolAddress(&qv, g_q);
    cudaGetSymbolAddress(&kv, g_k);
    cudaGetSymbolAddress(&vv, g_v);
    cudaGetSymbolAddress(&cv, g_ctx);
    float* q   = (float*)qv;
    float* k   = (float*)kv;
    float* v   = (float*)vv;
    float* ctx = (float*)cv;

    dim3 g1(Dc / 128, Mtot / 128);   // (8, 32)
    mma_gemm<1><<<g1, 256>>>(x, Wq, bq, q, 0.125f);   // 1/sqrt(64)
    mma_gemm<1><<<g1, 256>>>(x, Wk, bk, k, 1.0f);
    mma_gemm<1><<<g1, 256>>>(x, Wv, bv, v, 1.0f);

    fattn<<<dim3(Sc / 128, Bc * Hc), 256>>>(q, k, v, mask, ctx);

    mma_gemm<0><<<g1, 256>>>(ctx, Wo, bo, out, 1.0f);
}